// round 8
// baseline (speedup 1.0000x reference)
#include <cuda_runtime.h>
#include <cstdint>

#define FULLMASK 0xffffffffu

constexpr int D        = 128;   // embedding dim
constexpr int K        = 64;    // categorical dim
constexpr int BM       = 64;    // rows per block
constexpr int NTHREADS = 256;
constexpr int NNEG     = 5;
constexpr int NMAX     = 100000;
constexpr int MAXBLOCKS = 4096;

// device-global scratch (statics are allowed; no runtime allocs)
// __align__(16): device arrays only guarantee element alignment, but we do
// float4/float2 accesses into these.
__device__ __align__(16) float g_WT[D * K];             // W transposed [d][k]
__device__ __align__(16) float g_PC[(size_t)NMAX * K];  // ctx_emb  @ W^T
__device__ __align__(16) float g_PN[(size_t)NMAX * K];  // node_emb @ W^T
__device__ float        g_partials[MAXBLOCKS];
__device__ unsigned int g_counter = 0;

// ---------------- packed f32x2 helpers ----------------
__device__ __forceinline__ unsigned long long fma2(unsigned long long a,
                                                   unsigned long long b,
                                                   unsigned long long c) {
    unsigned long long r;
    asm("fma.rn.f32x2 %0, %1, %2, %3;" : "=l"(r) : "l"(a), "l"(b), "l"(c));
    return r;
}
__device__ __forceinline__ unsigned long long dup2(float x) {
    unsigned long long r;
    asm("mov.b64 %0, {%1, %2};" : "=l"(r) : "f"(x), "f"(x));
    return r;
}
__device__ __forceinline__ unsigned long long pack2(float x, float y) {
    unsigned long long r;
    asm("mov.b64 %0, {%1, %2};" : "=l"(r) : "f"(x), "f"(y));
    return r;
}
__device__ __forceinline__ float2 unpk(unsigned long long v) {
    float2 f;
    asm("mov.b64 {%0, %1}, %2;" : "=f"(f.x), "=f"(f.y) : "l"(v));
    return f;
}

__device__ __forceinline__ float wsum(float v) {
    #pragma unroll
    for (int o = 16; o > 0; o >>= 1) v += __shfl_xor_sync(FULLMASK, v, o);
    return v;
}
__device__ __forceinline__ float wmax(float v) {
    #pragma unroll
    for (int o = 16; o > 0; o >>= 1) v = fmaxf(v, __shfl_xor_sync(FULLMASK, v, o));
    return v;
}
__device__ __forceinline__ float log_sigmoid(float x) {
    float e = __expf(-fabsf(x));
    return fminf(x, 0.0f) - __logf(1.0f + e);
}

// =============================================================================
// One-time: transpose community_w into g_WT[d][k]
// =============================================================================
__global__ void gcn_wt_setup(const float* __restrict__ Wg)
{
    int i = blockIdx.x * blockDim.x + threadIdx.x;   // 2048 float4s
    if (i >= K * D / 4) return;
    float4 v = ((const float4*)Wg)[i];
    int k  = i >> 5;            // row of community_w (32 float4 per row)
    int d0 = (i & 31) << 2;
    g_WT[(d0 + 0) * K + k] = v.x;
    g_WT[(d0 + 1) * K + k] = v.y;
    g_WT[(d0 + 2) * K + k] = v.z;
    g_WT[(d0 + 3) * K + k] = v.w;
}

// =============================================================================
// Precompute PC = ctx_emb @ W^T and PN = node_emb @ W^T.
// Virtual rows [0,N) -> ctx -> PC; [N,2N) -> node -> PN. 64 rows per block.
// f32x2 packs ROW PAIRS. smem sA[d][col] with quarter-swizzle (conflict-free).
// =============================================================================
__global__ __launch_bounds__(NTHREADS, 4)
void gcn_precompute(const float* __restrict__ ctx,
                    const float* __restrict__ node,
                    int N, int total)
{
    __shared__ float sA[D * BM];   // 32KB
    const int tid  = threadIdx.x;
    const int lane = tid & 31;
    const int warp = tid >> 5;
    const int b0   = blockIdx.x * BM;

    // stage 64 rows (4 threads per row, quarter of D each), swizzled
    {
        int r  = tid >> 2;
        int q4 = tid & 3;
        int vr = min(b0 + r, total - 1);
        bool isctx = vr < N;
        const float* src = isctx ? ctx + (size_t)vr * D
                                 : node + (size_t)(vr - N) * D;
        const float4* sp = (const float4*)(src + q4 * 32);
        int col = r ^ (q4 << 3);
        #pragma unroll
        for (int j = 0; j < 8; j++) {
            float4 v = isctx ? __ldcs(sp + j) : __ldg(sp + j);
            int d0 = q4 * 32 + j * 4;
            sA[(d0 + 0) * BM + col] = v.x;
            sA[(d0 + 1) * BM + col] = v.y;
            sA[(d0 + 2) * BM + col] = v.z;
            sA[(d0 + 3) * BM + col] = v.w;
        }
    }
    __syncthreads();

    // GEMM: thread = row-pair (rp) x 8 k-columns
    const int rp = warp * 4 + (lane >> 3);     // 0..31
    const int k0 = (lane & 7) * 8;
    const int r0 = rp * 2;

    unsigned long long acc[8];
    #pragma unroll
    for (int j = 0; j < 8; j++) acc[j] = 0ull;

    #pragma unroll 4
    for (int d = 0; d < D; d++) {
        int col = r0 ^ ((d >> 5) << 3);
        float2 a2 = *(const float2*)&sA[d * BM + col];
        unsigned long long av = pack2(a2.x, a2.y);
        const float4* Wr = (const float4*)(g_WT + d * K + k0);
        float4 wa = __ldg(Wr);
        float4 wb = __ldg(Wr + 1);
        acc[0] = fma2(av, dup2(wa.x), acc[0]);
        acc[1] = fma2(av, dup2(wa.y), acc[1]);
        acc[2] = fma2(av, dup2(wa.z), acc[2]);
        acc[3] = fma2(av, dup2(wa.w), acc[3]);
        acc[4] = fma2(av, dup2(wb.x), acc[4]);
        acc[5] = fma2(av, dup2(wb.y), acc[5]);
        acc[6] = fma2(av, dup2(wb.z), acc[6]);
        acc[7] = fma2(av, dup2(wb.w), acc[7]);
    }

    // write both rows
    float2 t[8];
    #pragma unroll
    for (int j = 0; j < 8; j++) t[j] = unpk(acc[j]);
    int vr0 = b0 + r0;
    int vr1 = vr0 + 1;
    if (vr0 < total) {
        float* dst = (vr0 < N) ? g_PC + (size_t)vr0 * K
                               : g_PN + (size_t)(vr0 - N) * K;
        *(float4*)(dst + k0)     = make_float4(t[0].x, t[1].x, t[2].x, t[3].x);
        *(float4*)(dst + k0 + 4) = make_float4(t[4].x, t[5].x, t[6].x, t[7].x);
    }
    if (vr1 < total) {
        float* dst = (vr1 < N) ? g_PC + (size_t)vr1 * K
                               : g_PN + (size_t)(vr1 - N) * K;
        *(float4*)(dst + k0)     = make_float4(t[0].y, t[1].y, t[2].y, t[3].y);
        *(float4*)(dst + k0 + 4) = make_float4(t[4].y, t[5].y, t[6].y, t[7].y);
    }
}

// =============================================================================
// Main kernel: gather + q GEMM + softmax(q) + argmax + prior via PN lookup +
// loss via PC lookups + deterministic reduction.
// =============================================================================
__global__ __launch_bounds__(NTHREADS, 4)
void gcn_main(const int*   __restrict__ widx,
              const int*   __restrict__ cidx,
              const int*   __restrict__ negidx,
              const float* __restrict__ gumbel,
              const float* __restrict__ node_emb,
              float*       __restrict__ out0,
              float*       __restrict__ outq,
              float*       __restrict__ outp,
              int Btot, float invB)
{
    __shared__ float sA[D * BM];   // 32KB; later first 16KB overlays sQ[BM][K]
    __shared__ int   skst[BM];
    __shared__ float sred[8];
    __shared__ int   s_last;

    const int tid  = threadIdx.x;
    const int lane = tid & 31;
    const int warp = tid >> 5;
    const int b0   = blockIdx.x * BM;

    // ---- Phase 1: gather w_e, c_e; store prod swizzled ----
    {
        int r  = tid >> 2;
        int q4 = tid & 3;
        int b  = min(b0 + r, Btot - 1);
        int wi = widx[b];
        int ci = cidx[b];
        const float4* wp = (const float4*)(node_emb + (size_t)wi * D + q4 * 32);
        const float4* cp = (const float4*)(node_emb + (size_t)ci * D + q4 * 32);
        int col = r ^ (q4 << 3);
        #pragma unroll
        for (int j = 0; j < 8; j++) {
            float4 a = __ldg(wp + j);
            float4 c = __ldg(cp + j);
            int d0 = q4 * 32 + j * 4;
            sA[(d0 + 0) * BM + col] = a.x * c.x;
            sA[(d0 + 1) * BM + col] = a.y * c.y;
            sA[(d0 + 2) * BM + col] = a.z * c.z;
            sA[(d0 + 3) * BM + col] = a.w * c.w;
        }
    }
    __syncthreads();

    // ---- Phase 2: q GEMM (row-pair f32x2 x 8 k) ----
    const int rp = warp * 4 + (lane >> 3);
    const int k0 = (lane & 7) * 8;
    const int r0 = rp * 2;

    unsigned long long acc[8];
    #pragma unroll
    for (int j = 0; j < 8; j++) acc[j] = 0ull;

    #pragma unroll 4
    for (int d = 0; d < D; d++) {
        int col = r0 ^ ((d >> 5) << 3);
        float2 a2 = *(const float2*)&sA[d * BM + col];
        unsigned long long av = pack2(a2.x, a2.y);
        const float4* Wr = (const float4*)(g_WT + d * K + k0);
        float4 wa = __ldg(Wr);
        float4 wb = __ldg(Wr + 1);
        acc[0] = fma2(av, dup2(wa.x), acc[0]);
        acc[1] = fma2(av, dup2(wa.y), acc[1]);
        acc[2] = fma2(av, dup2(wa.z), acc[2]);
        acc[3] = fma2(av, dup2(wa.w), acc[3]);
        acc[4] = fma2(av, dup2(wb.x), acc[4]);
        acc[5] = fma2(av, dup2(wb.y), acc[5]);
        acc[6] = fma2(av, dup2(wb.z), acc[6]);
        acc[7] = fma2(av, dup2(wb.w), acc[7]);
    }
    __syncthreads();

    // ---- Phase 3: dump q logits to sQ (overlays sA) ----
    float* sQ = sA;   // [BM][K] = 16KB
    {
        float2 t[8];
        #pragma unroll
        for (int j = 0; j < 8; j++) t[j] = unpk(acc[j]);
        *(float4*)&sQ[r0 * K + k0]           = make_float4(t[0].x, t[1].x, t[2].x, t[3].x);
        *(float4*)&sQ[r0 * K + k0 + 4]       = make_float4(t[4].x, t[5].x, t[6].x, t[7].x);
        *(float4*)&sQ[(r0 + 1) * K + k0]     = make_float4(t[0].y, t[1].y, t[2].y, t[3].y);
        *(float4*)&sQ[(r0 + 1) * K + k0 + 4] = make_float4(t[4].y, t[5].y, t[6].y, t[7].y);
    }
    __syncthreads();

    // ---- Phase 4a: per-warp rows — softmax(q), argmax, prior via PN lookup ----
    for (int j = 0; j < 8; j++) {
        int r = warp * 8 + j;
        int b = b0 + r;
        if (b >= Btot) break;

        int wi = widx[b];
        float2 pn = __ldg((const float2*)(g_PN + (size_t)wi * K) + lane);
        float g1 = __ldcs(gumbel + (size_t)b * K + lane);
        float g2 = __ldcs(gumbel + (size_t)b * K + 32 + lane);
        float q1 = sQ[r * K + lane];
        float q2 = sQ[r * K + 32 + lane];

        // argmax(q + gumbel)
        float av = q1 + g1;
        int   ai = lane;
        {
            float a2v = q2 + g2;
            if (a2v > av) { av = a2v; ai = lane + 32; }
        }
        float    mv  = wmax(av);
        unsigned msk = __ballot_sync(FULLMASK, av == mv);
        int      kst = __shfl_sync(FULLMASK, ai, __ffs(msk) - 1);
        if (lane == 0) skst[r] = kst;

        // softmax(q)
        float mq  = wmax(fmaxf(q1, q2));
        float e1  = __expf(q1 - mq);
        float e2  = __expf(q2 - mq);
        float inv = __fdividef(1.0f, wsum(e1 + e2));
        __stcs(outq + (size_t)b * K + lane,      e1 * inv);
        __stcs(outq + (size_t)b * K + 32 + lane, e2 * inv);

        // softmax(prior) from PN row (lane holds k=2*lane, 2*lane+1).
        // NOTE: outp is at an ODD float offset in d_out -> scalar stores only.
        float mp = wmax(fmaxf(pn.x, pn.y));
        float f1 = __expf(pn.x - mp);
        float f2 = __expf(pn.y - mp);
        float ip = __fdividef(1.0f, wsum(f1 + f2));
        float* pdst = outp + (size_t)b * K + 2 * lane;
        __stcs(pdst,     f1 * ip);
        __stcs(pdst + 1, f2 * ip);
    }
    __syncwarp();

    // ---- Phase 4b: loss via PC lookups — 48 items per warp, fully parallel ----
    // item i (0..47): row j = i/6, slot = i%6 (0 -> positive ctx, 1..5 -> negs)
    float lacc = 0.0f;
    {
        // first item: i = lane (all 32 lanes)
        int j1 = lane / 6;
        int s1 = lane - 6 * j1;
        bool ok1 = (j1 < 8);
        int b1 = b0 + warp * 8 + (ok1 ? j1 : 0);
        if (b1 >= Btot) ok1 = false;
        // second item: i = 32 + lane (lanes 0..15)
        int i2 = 32 + lane;
        int j2 = i2 / 6;
        int s2 = i2 - 6 * j2;
        bool ok2 = (lane < 16);
        int b2 = b0 + warp * 8 + (ok2 ? j2 : 0);
        if (b2 >= Btot) ok2 = false;

        float v1 = 0.0f, v2 = 0.0f;
        int sl1 = 1, sl2 = 1;
        if (ok1) {
            int idx = (s1 == 0) ? cidx[b1] : negidx[(size_t)b1 * NNEG + s1 - 1];
            int kk  = skst[warp * 8 + j1];
            v1 = __ldg(&g_PC[(size_t)idx * K + kk]);
            sl1 = s1;
        }
        if (ok2) {
            int idx = (s2 == 0) ? cidx[b2] : negidx[(size_t)b2 * NNEG + s2 - 1];
            int kk  = skst[warp * 8 + j2];
            v2 = __ldg(&g_PC[(size_t)idx * K + kk]);
            sl2 = s2;
        }
        if (ok1) lacc += (sl1 == 0) ? log_sigmoid(v1) : 0.2f * log_sigmoid(-v1);
        if (ok2) lacc += (sl2 == 0) ? log_sigmoid(v2) : 0.2f * log_sigmoid(-v2);
    }
    lacc = wsum(lacc);
    if (lane == 0) sred[warp] = lacc;
    __syncthreads();

    // ---- block partial + deterministic last-block reduce ----
    if (tid == 0) {
        float s = 0.0f;
        #pragma unroll
        for (int i = 0; i < 8; i++) s += sred[i];
        g_partials[blockIdx.x] = s;
        __threadfence();
        unsigned t = atomicAdd(&g_counter, 1u);
        s_last = (t == gridDim.x - 1) ? 1 : 0;
    }
    __syncthreads();

    if (s_last) {
        float s = 0.0f;
        for (int i = tid; i < (int)gridDim.x; i += NTHREADS)
            s += __ldcg(&g_partials[i]);
        sA[tid] = s;
        __syncthreads();
        #pragma unroll
        for (int o = NTHREADS / 2; o > 0; o >>= 1) {
            if (tid < o) sA[tid] += sA[tid + o];
            __syncthreads();
        }
        if (tid == 0) {
            out0[0] = -sA[0] * invB;
            g_counter = 0;
        }
    }
}

// =============================================================================
extern "C" void kernel_launch(void* const* d_in, const int* in_sizes, int n_in,
                              void* d_out, int out_size)
{
    const int*   w        = (const int*)  d_in[0];
    const int*   c        = (const int*)  d_in[1];
    const int*   neg      = (const int*)  d_in[2];
    // d_in[3] = temp (==1): only rescales the argmax input -> irrelevant
    const float* gumbel   = (const float*)d_in[4];
    const float* node_emb = (const float*)d_in[5];
    const float* ctx_emb  = (const float*)d_in[6];
    const float* Wg       = (const float*)d_in[7];

    const int B = in_sizes[0];
    int N = in_sizes[5] / D;           // node count (100000)
    if (N > NMAX) N = NMAX;

    float* out       = (float*)d_out;
    float* out_q     = out + 1;
    float* out_prior = out + 1 + (size_t)B * K;

    int nb = (B + BM - 1) / BM;        // 2048
    if (nb > MAXBLOCKS) nb = MAXBLOCKS;
    int pb = (2 * N + BM - 1) / BM;    // 3125

    gcn_wt_setup<<<(K * D / 4 + 255) / 256, 256>>>(Wg);
    gcn_precompute<<<pb, NTHREADS>>>(ctx_emb, node_emb, N, 2 * N);
    gcn_main<<<nb, NTHREADS>>>(w, c, neg, gumbel, node_emb,
                               out, out_q, out_prior, B, 1.0f / (float)B);
}

// round 10
// speedup vs baseline: 1.9462x; 1.9462x over previous
#include <cuda_runtime.h>
#include <cstdint>

#define FULLMASK 0xffffffffu

constexpr int D        = 128;   // embedding dim
constexpr int K        = 64;    // categorical dim
constexpr int BM       = 64;    // batch rows per block
constexpr int NTHREADS = 512;   // 16 warps
constexpr int NNEG     = 5;
constexpr int MAXBLOCKS = 4096;

// device-global scratch (no runtime allocs)
__device__ __align__(16) float g_WT[D * K];   // W transposed [d][k], 32KB, L1-hot
__device__ float        g_partials[MAXBLOCKS];
__device__ unsigned int g_counter = 0;

// dynamic smem: sPW [d][b][2] (prod, w_e) pairs = 64KB; phase-3 overlays sQ/sP.
constexpr int SPW_FLOATS = D * BM * 2;               // 16384
constexpr int SMEM_BYTES = SPW_FLOATS * 4;           // 65536 -> 2 blocks/SM

// ---------------- packed f32x2 helpers (PTX-only on Blackwell) ----------------
__device__ __forceinline__ unsigned long long fma2(unsigned long long a,
                                                   unsigned long long b,
                                                   unsigned long long c) {
    unsigned long long r;
    asm("fma.rn.f32x2 %0, %1, %2, %3;" : "=l"(r) : "l"(a), "l"(b), "l"(c));
    return r;
}
__device__ __forceinline__ unsigned long long dup2(float x) {
    unsigned long long r;
    asm("mov.b64 %0, {%1, %2};" : "=l"(r) : "f"(x), "f"(x));
    return r;
}
__device__ __forceinline__ float2 unpk(unsigned long long v) {
    float2 f;
    asm("mov.b64 {%0, %1}, %2;" : "=f"(f.x), "=f"(f.y) : "l"(v));
    return f;
}

__device__ __forceinline__ float wsum(float v) {
    #pragma unroll
    for (int o = 16; o > 0; o >>= 1) v += __shfl_xor_sync(FULLMASK, v, o);
    return v;
}
__device__ __forceinline__ float wmax(float v) {
    #pragma unroll
    for (int o = 16; o > 0; o >>= 1) v = fmaxf(v, __shfl_xor_sync(FULLMASK, v, o));
    return v;
}
__device__ __forceinline__ float dot4(float4 a, float4 b) {
    return fmaf(a.x, b.x, fmaf(a.y, b.y, fmaf(a.z, b.z, a.w * b.w)));
}
__device__ __forceinline__ float log_sigmoid(float x) {
    float e = __expf(-fabsf(x));
    return fminf(x, 0.0f) - __logf(1.0f + e);
}

// =============================================================================
// One-time: transpose community_w into g_WT[d][k]
// =============================================================================
__global__ void gcn_wt_setup(const float* __restrict__ Wg)
{
    int i = blockIdx.x * blockDim.x + threadIdx.x;   // 2048 float4s
    if (i >= K * D / 4) return;
    float4 v = ((const float4*)Wg)[i];
    int k  = i >> 5;            // row of community_w (32 float4 per row)
    int d0 = (i & 31) << 2;
    g_WT[(d0 + 0) * K + k] = v.x;
    g_WT[(d0 + 1) * K + k] = v.y;
    g_WT[(d0 + 2) * K + k] = v.z;
    g_WT[(d0 + 3) * K + k] = v.w;
}

// =============================================================================
// Fused kernel (r5 algorithm, 512-thread geometry for 32 warps/SM):
// gather + dual GEMM (f32x2) + softmax/argmax + loss + deterministic reduce.
// =============================================================================
__global__ __launch_bounds__(NTHREADS, 2)
void gcn_gumbel_mega(const int*   __restrict__ widx,
                     const int*   __restrict__ cidx,
                     const int*   __restrict__ negidx,
                     const float* __restrict__ gumbel,
                     const float* __restrict__ node_emb,
                     const float* __restrict__ ctx_emb,
                     const float* __restrict__ Wg,       // community_w [K][D]
                     float*       __restrict__ out0,     // loss scalar
                     float*       __restrict__ outq,     // softmax(q)  [B][K]
                     float*       __restrict__ outp,     // prior       [B][K]
                     int Btot, float invB)
{
    extern __shared__ float smem[];
    float* sPW = smem;                 // [d][b][2] (prod, w_e)

    __shared__ float sred[16];
    __shared__ int   s_last;

    const int tid  = threadIdx.x;
    const int lane = tid & 31;
    const int warp = tid >> 5;         // 0..15
    const int b0   = blockIdx.x * BM;

    // ---------------- Phase 1: embedding gathers -> smem pairs ----------------
    // 8 threads per batch row, each covers 16 floats (4 float4) of D.
    {
        int r  = tid >> 3;             // 0..63 local row
        int e  = tid & 7;              // eighth of D
        int b  = min(b0 + r, Btot - 1);
        int wi = widx[b];
        int ci = cidx[b];
        const float4* wp = (const float4*)(node_emb + (size_t)wi * D + e * 16);
        const float4* cp = (const float4*)(node_emb + (size_t)ci * D + e * 16);
        float2* dst = (float2*)sPW;    // pair index = d*BM + r
        #pragma unroll
        for (int j = 0; j < 4; j++) {
            float4 a  = wp[j];
            float4 bb = cp[j];
            int dbase = e * 16 + j * 4;
            dst[(dbase + 0) * BM + r] = make_float2(a.x * bb.x, a.x);
            dst[(dbase + 1) * BM + r] = make_float2(a.y * bb.y, a.y);
            dst[(dbase + 2) * BM + r] = make_float2(a.z * bb.z, a.z);
            dst[(dbase + 3) * BM + r] = make_float2(a.w * bb.w, a.w);
        }
    }
    __syncthreads();

    // ---------------- Phase 2: dual GEMM via packed f32x2 ----------------
    // thread tile: 2 batch rows x 4 k columns (512 threads x 8 = 64x64 outputs)
    const int tx = tid & 15;       // k-group
    const int ty = tid >> 4;       // 0..31 row-pair group
    const int kb = tx * 4;
    const int rb = ty * 2;

    unsigned long long acc[2][4];
    #pragma unroll
    for (int i = 0; i < 2; i++)
        #pragma unroll
        for (int j = 0; j < 4; j++) acc[i][j] = 0ull;

    #pragma unroll 4
    for (int d = 0; d < D; d++) {
        const float4 wv = __ldg((const float4*)(g_WT + (size_t)d * K + kb));
        unsigned long long w0 = dup2(wv.x);
        unsigned long long w1 = dup2(wv.y);
        unsigned long long w2 = dup2(wv.z);
        unsigned long long w3 = dup2(wv.w);
        const unsigned long long* pw =
            (const unsigned long long*)(sPW + (size_t)(d * BM + rb) * 2);
        unsigned long long a0 = pw[0];
        unsigned long long a1 = pw[1];
        acc[0][0] = fma2(a0, w0, acc[0][0]);
        acc[0][1] = fma2(a0, w1, acc[0][1]);
        acc[0][2] = fma2(a0, w2, acc[0][2]);
        acc[0][3] = fma2(a0, w3, acc[0][3]);
        acc[1][0] = fma2(a1, w0, acc[1][0]);
        acc[1][1] = fma2(a1, w1, acc[1][1]);
        acc[1][2] = fma2(a1, w2, acc[1][2]);
        acc[1][3] = fma2(a1, w3, acc[1][3]);
    }
    __syncthreads();   // all phase-2 reads of sPW done before overlay

    // ---------------- Phase 3: dump q / prior logits (vectorized) -------------
    float* sQ = smem;            // [BM][K] = 16KB
    float* sP = smem + BM * K;   // [BM][K] = 16KB
    #pragma unroll
    for (int i = 0; i < 2; i++) {
        float2 t0 = unpk(acc[i][0]);
        float2 t1 = unpk(acc[i][1]);
        float2 t2 = unpk(acc[i][2]);
        float2 t3 = unpk(acc[i][3]);
        *(float4*)&sQ[(rb + i) * K + kb] = make_float4(t0.x, t1.x, t2.x, t3.x);
        *(float4*)&sP[(rb + i) * K + kb] = make_float4(t0.y, t1.y, t2.y, t3.y);
    }
    __syncthreads();

    // ---------------- Phase 4+5: per-warp rows (4 rows per warp) -------------
    float lacc = 0.0f;
    for (int j = 0; j < 4; j++) {
        int r = warp * 4 + j;
        int b = b0 + r;
        if (b >= Btot) break;

        float q1 = sQ[r * K + lane];
        float q2 = sQ[r * K + 32 + lane];
        float p1 = sP[r * K + lane];
        float p2 = sP[r * K + 32 + lane];
        float g1 = __ldcs(gumbel + (size_t)b * K + lane);
        float g2 = __ldcs(gumbel + (size_t)b * K + 32 + lane);

        // softmax(q)
        float mq  = wmax(fmaxf(q1, q2));
        float e1  = __expf(q1 - mq);
        float e2  = __expf(q2 - mq);
        float inv = __fdividef(1.0f, wsum(e1 + e2));
        __stcs(outq + (size_t)b * K + lane,      e1 * inv);
        __stcs(outq + (size_t)b * K + 32 + lane, e2 * inv);

        // argmax(q + gumbel): per-lane best, warp max, ballot leader
        float av = q1 + g1;
        int   ai = lane;
        {
            float a2v = q2 + g2;
            if (a2v > av) { av = a2v; ai = lane + 32; }
        }
        float    mv  = wmax(av);
        unsigned msk = __ballot_sync(FULLMASK, av == mv);
        int      kst = __shfl_sync(FULLMASK, ai, __ffs(msk) - 1);

        // softmax(prior logits)
        float mp = wmax(fmaxf(p1, p2));
        float f1 = __expf(p1 - mp);
        float f2 = __expf(p2 - mp);
        float ip = __fdividef(1.0f, wsum(f1 + f2));
        __stcs(outp + (size_t)b * K + lane,      f1 * ip);
        __stcs(outp + (size_t)b * K + 32 + lane, f2 * ip);

        // loss dots with W[k*] (hot 32KB table -> L1)
        int ci = cidx[b];
        float4 wv = *(const float4*)(Wg + (size_t)kst * D + (lane << 2));
        float4 cv = *(const float4*)(ctx_emb + (size_t)ci * D + (lane << 2));
        float s0 = dot4(wv, cv);
        float s1, s2, s3, s4, s5;
        {
            int n0 = negidx[(size_t)b * NNEG + 0];
            int n1 = negidx[(size_t)b * NNEG + 1];
            int n2 = negidx[(size_t)b * NNEG + 2];
            int n3 = negidx[(size_t)b * NNEG + 3];
            int n4 = negidx[(size_t)b * NNEG + 4];
            float4 v0 = *(const float4*)(ctx_emb + (size_t)n0 * D + (lane << 2));
            float4 v1 = *(const float4*)(ctx_emb + (size_t)n1 * D + (lane << 2));
            float4 v2 = *(const float4*)(ctx_emb + (size_t)n2 * D + (lane << 2));
            float4 v3 = *(const float4*)(ctx_emb + (size_t)n3 * D + (lane << 2));
            float4 v4 = *(const float4*)(ctx_emb + (size_t)n4 * D + (lane << 2));
            s1 = dot4(wv, v0);
            s2 = dot4(wv, v1);
            s3 = dot4(wv, v2);
            s4 = dot4(wv, v3);
            s5 = dot4(wv, v4);
        }
        s0 = wsum(s0); s1 = wsum(s1); s2 = wsum(s2);
        s3 = wsum(s3); s4 = wsum(s4); s5 = wsum(s5);

        float term = log_sigmoid(s0);
        float nsum = log_sigmoid(-s1) + log_sigmoid(-s2) + log_sigmoid(-s3)
                   + log_sigmoid(-s4) + log_sigmoid(-s5);
        term = fmaf(nsum, 1.0f / (float)NNEG, term);
        if (lane == 0) lacc += term;
    }

    // ---------------- Block partial + last-block deterministic reduce ---------
    if (lane == 0) sred[warp] = lacc;
    __syncthreads();
    if (tid == 0) {
        float s = 0.0f;
        #pragma unroll
        for (int i = 0; i < 16; i++) s += sred[i];
        g_partials[blockIdx.x] = s;
        __threadfence();
        unsigned t = atomicAdd(&g_counter, 1u);
        s_last = (t == gridDim.x - 1) ? 1 : 0;
    }
    __syncthreads();

    if (s_last) {
        float s = 0.0f;
        for (int i = tid; i < (int)gridDim.x; i += NTHREADS)
            s += __ldcg(&g_partials[i]);
        smem[tid] = s;
        __syncthreads();
        #pragma unroll
        for (int o = NTHREADS / 2; o > 0; o >>= 1) {
            if (tid < o) smem[tid] += smem[tid + o];
            __syncthreads();
        }
        if (tid == 0) {
            out0[0] = -smem[0] * invB;
            g_counter = 0;   // reset for next (graph-replayed) launch
        }
    }
}

// =============================================================================
extern "C" void kernel_launch(void* const* d_in, const int* in_sizes, int n_in,
                              void* d_out, int out_size)
{
    const int*   w        = (const int*)  d_in[0];
    const int*   c        = (const int*)  d_in[1];
    const int*   neg      = (const int*)  d_in[2];
    // d_in[3] = temp (==1): only rescales the argmax input -> provably irrelevant
    const float* gumbel   = (const float*)d_in[4];
    const float* node_emb = (const float*)d_in[5];
    const float* ctx_emb  = (const float*)d_in[6];
    const float* Wg       = (const float*)d_in[7];

    const int B = in_sizes[0];

    float* out       = (float*)d_out;
    float* out_q     = out + 1;
    float* out_prior = out + 1 + (size_t)B * K;

    int nb = (B + BM - 1) / BM;     // 2048 for B=131072
    if (nb > MAXBLOCKS) nb = MAXBLOCKS;

    cudaFuncSetAttribute(gcn_gumbel_mega,
                         cudaFuncAttributeMaxDynamicSharedMemorySize, SMEM_BYTES);

    gcn_wt_setup<<<(K * D / 4 + 255) / 256, 256>>>(Wg);
    gcn_gumbel_mega<<<nb, NTHREADS, SMEM_BYTES>>>(
        w, c, neg, gumbel, node_emb, ctx_emb, Wg,
        out, out_q, out_prior, B, 1.0f / (float)B);
}

// round 12
// speedup vs baseline: 2.1848x; 1.1226x over previous
#include <cuda_runtime.h>
#include <cstdint>

#define FULLMASK 0xffffffffu

constexpr int D        = 128;   // embedding dim
constexpr int K        = 64;    // categorical dim
constexpr int BM       = 64;    // batch rows per block
constexpr int NTHREADS = 256;
constexpr int NNEG     = 5;
constexpr int MAXBLOCKS = 4096;

// device-global scratch (no runtime allocs)
__device__ __align__(16) float g_WT[D * K];   // W transposed [d][k], 32KB, L1-hot
__device__ float        g_partials[MAXBLOCKS];
__device__ unsigned int g_counter = 0;

// dynamic smem: sPW [d][b][2] (prod, w_e) pairs = 64KB; phase-3 overlays sQ/sP.
constexpr int SPW_FLOATS = D * BM * 2;               // 16384
constexpr int SMEM_BYTES = SPW_FLOATS * 4;           // 65536 -> 3 blocks/SM

// ---------------- packed f32x2 helpers (PTX-only on Blackwell) ----------------
__device__ __forceinline__ unsigned long long fma2(unsigned long long a,
                                                   unsigned long long b,
                                                   unsigned long long c) {
    unsigned long long r;
    asm("fma.rn.f32x2 %0, %1, %2, %3;" : "=l"(r) : "l"(a), "l"(b), "l"(c));
    return r;
}
__device__ __forceinline__ unsigned long long dup2(float x) {
    unsigned long long r;
    asm("mov.b64 %0, {%1, %2};" : "=l"(r) : "f"(x), "f"(x));
    return r;
}
__device__ __forceinline__ float2 unpk(unsigned long long v) {
    float2 f;
    asm("mov.b64 {%0, %1}, %2;" : "=f"(f.x), "=f"(f.y) : "l"(v));
    return f;
}

__device__ __forceinline__ float wsum(float v) {
    #pragma unroll
    for (int o = 16; o > 0; o >>= 1) v += __shfl_xor_sync(FULLMASK, v, o);
    return v;
}
__device__ __forceinline__ float wmax(float v) {
    #pragma unroll
    for (int o = 16; o > 0; o >>= 1) v = fmaxf(v, __shfl_xor_sync(FULLMASK, v, o));
    return v;
}
__device__ __forceinline__ float dot4(float4 a, float4 b) {
    return fmaf(a.x, b.x, fmaf(a.y, b.y, fmaf(a.z, b.z, a.w * b.w)));
}
__device__ __forceinline__ float log_sigmoid(float x) {
    float e = __expf(-fabsf(x));
    return fminf(x, 0.0f) - __logf(1.0f + e);
}

// =============================================================================
// One-time: transpose community_w into g_WT[d][k]
// =============================================================================
__global__ void gcn_wt_setup(const float* __restrict__ Wg)
{
    int i = blockIdx.x * blockDim.x + threadIdx.x;   // 2048 float4s
    if (i >= K * D / 4) return;
    float4 v = ((const float4*)Wg)[i];
    int k  = i >> 5;            // row of community_w (32 float4 per row)
    int d0 = (i & 31) << 2;
    g_WT[(d0 + 0) * K + k] = v.x;
    g_WT[(d0 + 1) * K + k] = v.y;
    g_WT[(d0 + 2) * K + k] = v.z;
    g_WT[(d0 + 3) * K + k] = v.w;
}

// =============================================================================
// Fused kernel (r5 geometry: 256 threads, 3 blocks/SM, 4r x 4k tiles).
// LSU-instruction diet: GEMM A loads via 2x LDS.128 (was 4x LDS.64).
// =============================================================================
__global__ __launch_bounds__(NTHREADS, 3)
void gcn_gumbel_mega(const int*   __restrict__ widx,
                     const int*   __restrict__ cidx,
                     const int*   __restrict__ negidx,
                     const float* __restrict__ gumbel,
                     const float* __restrict__ node_emb,
                     const float* __restrict__ ctx_emb,
                     const float* __restrict__ Wg,       // community_w [K][D]
                     float*       __restrict__ out0,     // loss scalar
                     float*       __restrict__ outq,     // softmax(q)  [B][K]
                     float*       __restrict__ outp,     // prior       [B][K]
                     int Btot, float invB)
{
    extern __shared__ float smem[];
    float* sPW = smem;                 // [d][b][2] (prod, w_e)

    __shared__ float sred[8];
    __shared__ int   s_last;

    const int tid  = threadIdx.x;
    const int lane = tid & 31;
    const int warp = tid >> 5;
    const int b0   = blockIdx.x * BM;

    // ---------------- Phase 1: embedding gathers -> smem pairs ----------------
    {
        int r       = tid >> 2;        // 0..63 local row
        int quarter = tid & 3;         // 0..3
        int b       = min(b0 + r, Btot - 1);
        int wi = widx[b];
        int ci = cidx[b];
        const float4* wp = (const float4*)(node_emb + (size_t)wi * D + quarter * 32);
        const float4* cp = (const float4*)(node_emb + (size_t)ci * D + quarter * 32);
        float2* dst = (float2*)sPW;    // pair index = d*BM + r
        #pragma unroll
        for (int j = 0; j < 8; j++) {
            float4 a  = wp[j];
            float4 bb = cp[j];
            int dbase = quarter * 32 + j * 4;
            dst[(dbase + 0) * BM + r] = make_float2(a.x * bb.x, a.x);
            dst[(dbase + 1) * BM + r] = make_float2(a.y * bb.y, a.y);
            dst[(dbase + 2) * BM + r] = make_float2(a.z * bb.z, a.z);
            dst[(dbase + 3) * BM + r] = make_float2(a.w * bb.w, a.w);
        }
    }
    __syncthreads();

    // ---------------- Phase 2: dual GEMM via packed f32x2 ----------------
    // thread tile: 4 batch rows x 4 k columns. Per thread-d: 1 LDG.128 (W) +
    // 2 LDS.128 (four row-pairs, 32B contiguous & aligned) + 16 fma2.
    const int tx = tid & 15;       // k-group
    const int ty = tid >> 4;       // b-group
    const int kb = tx * 4;
    const int bb = ty * 4;

    unsigned long long acc[4][4];
    #pragma unroll
    for (int i = 0; i < 4; i++)
        #pragma unroll
        for (int j = 0; j < 4; j++) acc[i][j] = 0ull;

    #pragma unroll 4
    for (int d = 0; d < D; d++) {
        const float4 wv = __ldg((const float4*)(g_WT + (size_t)d * K + kb));
        unsigned long long w0 = dup2(wv.x);
        unsigned long long w1 = dup2(wv.y);
        unsigned long long w2 = dup2(wv.z);
        unsigned long long w3 = dup2(wv.w);
        // rows bb..bb+3: pairs are 32B contiguous, 32B aligned -> 2x LDS.128
        const ulonglong2* pw2 =
            (const ulonglong2*)(sPW + (size_t)(d * BM + bb) * 2);
        ulonglong2 A01 = pw2[0];
        ulonglong2 A23 = pw2[1];
        acc[0][0] = fma2(A01.x, w0, acc[0][0]);
        acc[0][1] = fma2(A01.x, w1, acc[0][1]);
        acc[0][2] = fma2(A01.x, w2, acc[0][2]);
        acc[0][3] = fma2(A01.x, w3, acc[0][3]);
        acc[1][0] = fma2(A01.y, w0, acc[1][0]);
        acc[1][1] = fma2(A01.y, w1, acc[1][1]);
        acc[1][2] = fma2(A01.y, w2, acc[1][2]);
        acc[1][3] = fma2(A01.y, w3, acc[1][3]);
        acc[2][0] = fma2(A23.x, w0, acc[2][0]);
        acc[2][1] = fma2(A23.x, w1, acc[2][1]);
        acc[2][2] = fma2(A23.x, w2, acc[2][2]);
        acc[2][3] = fma2(A23.x, w3, acc[2][3]);
        acc[3][0] = fma2(A23.y, w0, acc[3][0]);
        acc[3][1] = fma2(A23.y, w1, acc[3][1]);
        acc[3][2] = fma2(A23.y, w2, acc[3][2]);
        acc[3][3] = fma2(A23.y, w3, acc[3][3]);
    }
    __syncthreads();   // all phase-2 reads of sPW done before overlay

    // ---------------- Phase 3: dump q / prior logits (vectorized) -------------
    float* sQ = smem;            // [BM][K] = 16KB
    float* sP = smem + BM * K;   // [BM][K] = 16KB
    #pragma unroll
    for (int i = 0; i < 4; i++) {
        float2 t0 = unpk(acc[i][0]);
        float2 t1 = unpk(acc[i][1]);
        float2 t2 = unpk(acc[i][2]);
        float2 t3 = unpk(acc[i][3]);
        *(float4*)&sQ[(bb + i) * K + kb] = make_float4(t0.x, t1.x, t2.x, t3.x);
        *(float4*)&sP[(bb + i) * K + kb] = make_float4(t0.y, t1.y, t2.y, t3.y);
    }
    __syncthreads();

    // ---------------- Phase 4+5: per-warp rows (no cross-warp sync) -----------
    float lacc = 0.0f;
    for (int j = 0; j < 8; j++) {
        int r = warp * 8 + j;
        int b = b0 + r;
        if (b >= Btot) break;

        // ---- issue all independent loads first (latency overlap) ----
        int ci = cidx[b];
        int n0 = negidx[(size_t)b * NNEG + 0];
        int n1 = negidx[(size_t)b * NNEG + 1];
        int n2 = negidx[(size_t)b * NNEG + 2];
        int n3 = negidx[(size_t)b * NNEG + 3];
        int n4 = negidx[(size_t)b * NNEG + 4];
        float4 cv = *(const float4*)(ctx_emb + (size_t)ci * D + (lane << 2));
        float4 v0 = *(const float4*)(ctx_emb + (size_t)n0 * D + (lane << 2));
        float4 v1 = *(const float4*)(ctx_emb + (size_t)n1 * D + (lane << 2));
        float4 v2 = *(const float4*)(ctx_emb + (size_t)n2 * D + (lane << 2));
        float4 v3 = *(const float4*)(ctx_emb + (size_t)n3 * D + (lane << 2));
        float4 v4 = *(const float4*)(ctx_emb + (size_t)n4 * D + (lane << 2));
        float g1 = __ldcs(gumbel + (size_t)b * K + lane);
        float g2 = __ldcs(gumbel + (size_t)b * K + 32 + lane);
        float q1 = sQ[r * K + lane];
        float q2 = sQ[r * K + 32 + lane];
        float p1 = sP[r * K + lane];
        float p2 = sP[r * K + 32 + lane];

        // ---- argmax(q + gumbel) first, so the W[k*] gather flies early ----
        float av = q1 + g1;
        int   ai = lane;
        {
            float a2v = q2 + g2;
            if (a2v > av) { av = a2v; ai = lane + 32; }
        }
        float    mv  = wmax(av);
        unsigned msk = __ballot_sync(FULLMASK, av == mv);
        int      kst = __shfl_sync(FULLMASK, ai, __ffs(msk) - 1);
        float4 wv = *(const float4*)(Wg + (size_t)kst * D + (lane << 2));

        // ---- softmax(q) ----
        float mq  = wmax(fmaxf(q1, q2));
        float e1  = __expf(q1 - mq);
        float e2  = __expf(q2 - mq);
        float inv = __fdividef(1.0f, wsum(e1 + e2));
        __stcs(outq + (size_t)b * K + lane,      e1 * inv);
        __stcs(outq + (size_t)b * K + 32 + lane, e2 * inv);

        // ---- softmax(prior) ----
        float mp = wmax(fmaxf(p1, p2));
        float f1 = __expf(p1 - mp);
        float f2 = __expf(p2 - mp);
        float ip = __fdividef(1.0f, wsum(f1 + f2));
        __stcs(outp + (size_t)b * K + lane,      f1 * ip);
        __stcs(outp + (size_t)b * K + 32 + lane, f2 * ip);

        // ---- loss dots with W[k*] ----
        float s0 = dot4(wv, cv);
        float s1 = dot4(wv, v0);
        float s2 = dot4(wv, v1);
        float s3 = dot4(wv, v2);
        float s4 = dot4(wv, v3);
        float s5 = dot4(wv, v4);
        s0 = wsum(s0); s1 = wsum(s1); s2 = wsum(s2);
        s3 = wsum(s3); s4 = wsum(s4); s5 = wsum(s5);

        float term = log_sigmoid(s0);
        float nsum = log_sigmoid(-s1) + log_sigmoid(-s2) + log_sigmoid(-s3)
                   + log_sigmoid(-s4) + log_sigmoid(-s5);
        term = fmaf(nsum, 1.0f / (float)NNEG, term);
        if (lane == 0) lacc += term;
    }

    // ---------------- Block partial + last-block deterministic reduce ---------
    if (lane == 0) sred[warp] = lacc;
    __syncthreads();
    if (tid == 0) {
        float s = 0.0f;
        #pragma unroll
        for (int i = 0; i < 8; i++) s += sred[i];
        g_partials[blockIdx.x] = s;
        __threadfence();
        unsigned t = atomicAdd(&g_counter, 1u);
        s_last = (t == gridDim.x - 1) ? 1 : 0;
    }
    __syncthreads();

    if (s_last) {
        float s = 0.0f;
        for (int i = tid; i < (int)gridDim.x; i += NTHREADS)
            s += __ldcg(&g_partials[i]);
        smem[tid] = s;
        __syncthreads();
        #pragma unroll
        for (int o = NTHREADS / 2; o > 0; o >>= 1) {
            if (tid < o) smem[tid] += smem[tid + o];
            __syncthreads();
        }
        if (tid == 0) {
            out0[0] = -smem[0] * invB;
            g_counter = 0;   // reset for next (graph-replayed) launch
        }
    }
}

// =============================================================================
extern "C" void kernel_launch(void* const* d_in, const int* in_sizes, int n_in,
                              void* d_out, int out_size)
{
    const int*   w        = (const int*)  d_in[0];
    const int*   c        = (const int*)  d_in[1];
    const int*   neg      = (const int*)  d_in[2];
    // d_in[3] = temp (==1): only rescales the argmax input -> provably irrelevant
    const float* gumbel   = (const float*)d_in[4];
    const float* node_emb = (const float*)d_in[5];
    const float* ctx_emb  = (const float*)d_in[6];
    const float* Wg       = (const float*)d_in[7];

    const int B = in_sizes[0];

    float* out       = (float*)d_out;
    float* out_q     = out + 1;
    float* out_prior = out + 1 + (size_t)B * K;

    int nb = (B + BM - 1) / BM;     // 2048 for B=131072
    if (nb > MAXBLOCKS) nb = MAXBLOCKS;

    cudaFuncSetAttribute(gcn_gumbel_mega,
                         cudaFuncAttributeMaxDynamicSharedMemorySize, SMEM_BYTES);

    gcn_wt_setup<<<(K * D / 4 + 255) / 256, 256>>>(Wg);
    gcn_gumbel_mega<<<nb, NTHREADS, SMEM_BYTES>>>(
        w, c, neg, gumbel, node_emb, ctx_emb, Wg,
        out, out_q, out_prior, B, 1.0f / (float)B);
}

// round 15
// speedup vs baseline: 2.2664x; 1.0374x over previous
#include <cuda_runtime.h>
#include <cstdint>

#define FULLMASK 0xffffffffu

constexpr int D        = 128;   // embedding dim
constexpr int K        = 64;    // categorical dim
constexpr int BM       = 64;    // batch rows per block
constexpr int NTHREADS = 256;
constexpr int NNEG     = 5;
constexpr int MAXBLOCKS = 4096;

constexpr int QS = 68;          // padded sQ/sP row stride (272B) — conflict-free

// device-global scratch (no runtime allocs)
__device__ __align__(16) float g_WT[D * K];   // W transposed [d][k], 32KB, L1-hot
__device__ float        g_partials[MAXBLOCKS];
__device__ unsigned int g_counter = 0;

// dynamic smem: sPW [d][col][2] (prod, w_e) pairs = 64KB; overlay sQ/sP (QS-padded).
constexpr int SPW_FLOATS = D * BM * 2;               // 16384
constexpr int SMEM_BYTES = SPW_FLOATS * 4;           // 65536 -> 3 blocks/SM

// ---------------- packed f32x2 helpers (PTX-only on Blackwell) ----------------
__device__ __forceinline__ unsigned long long fma2(unsigned long long a,
                                                   unsigned long long b,
                                                   unsigned long long c) {
    unsigned long long r;
    asm("fma.rn.f32x2 %0, %1, %2, %3;" : "=l"(r) : "l"(a), "l"(b), "l"(c));
    return r;
}
__device__ __forceinline__ unsigned long long dup2(float x) {
    unsigned long long r;
    asm("mov.b64 %0, {%1, %2};" : "=l"(r) : "f"(x), "f"(x));
    return r;
}
__device__ __forceinline__ float2 unpk(unsigned long long v) {
    float2 f;
    asm("mov.b64 {%0, %1}, %2;" : "=f"(f.x), "=f"(f.y) : "l"(v));
    return f;
}

__device__ __forceinline__ float wsum(float v) {
    #pragma unroll
    for (int o = 16; o > 0; o >>= 1) v += __shfl_xor_sync(FULLMASK, v, o);
    return v;
}
__device__ __forceinline__ float wmax(float v) {
    #pragma unroll
    for (int o = 16; o > 0; o >>= 1) v = fmaxf(v, __shfl_xor_sync(FULLMASK, v, o));
    return v;
}
__device__ __forceinline__ float dot4(float4 a, float4 b) {
    return fmaf(a.x, b.x, fmaf(a.y, b.y, fmaf(a.z, b.z, a.w * b.w)));
}
__device__ __forceinline__ float log_sigmoid(float x) {
    float e = __expf(-fabsf(x));
    return fminf(x, 0.0f) - __logf(1.0f + e);
}

// =============================================================================
// One-time: transpose community_w into g_WT[d][k]
// =============================================================================
__global__ void gcn_wt_setup(const float* __restrict__ Wg)
{
    int i = blockIdx.x * blockDim.x + threadIdx.x;   // 2048 float4s
    if (i >= K * D / 4) return;
    float4 v = ((const float4*)Wg)[i];
    int k  = i >> 5;            // row of community_w (32 float4 per row)
    int d0 = (i & 31) << 2;
    g_WT[(d0 + 0) * K + k] = v.x;
    g_WT[(d0 + 1) * K + k] = v.y;
    g_WT[(d0 + 2) * K + k] = v.z;
    g_WT[(d0 + 3) * K + k] = v.w;
}

// =============================================================================
// Fused kernel (r12 base + bank-conflict fixes):
//  - sPW column swizzle: col = r ^ ((d>>5)<<3)  (phase-1 STS conflict-free)
//  - sQ/sP padded to QS=68 floats               (phase-3 STS conflict-free)
// =============================================================================
__global__ __launch_bounds__(NTHREADS, 3)
void gcn_gumbel_mega(const int*   __restrict__ widx,
                     const int*   __restrict__ cidx,
                     const int*   __restrict__ negidx,
                     const float* __restrict__ gumbel,
                     const float* __restrict__ node_emb,
                     const float* __restrict__ ctx_emb,
                     const float* __restrict__ Wg,       // community_w [K][D]
                     float*       __restrict__ out0,     // loss scalar
                     float*       __restrict__ outq,     // softmax(q)  [B][K]
                     float*       __restrict__ outp,     // prior       [B][K]
                     int Btot, float invB)
{
    extern __shared__ float smem[];
    float* sPW = smem;                 // [d][col][2] (prod, w_e), col swizzled

    __shared__ float sred[8];
    __shared__ int   s_last;

    const int tid  = threadIdx.x;
    const int lane = tid & 31;
    const int warp = tid >> 5;
    const int b0   = blockIdx.x * BM;

    // ---------------- Phase 1: embedding gathers -> smem pairs (swizzled) -----
    {
        int r       = tid >> 2;        // 0..63 local row
        int quarter = tid & 3;         // 0..3; covers d in [q*32, q*32+32)
        int b       = min(b0 + r, Btot - 1);
        int wi = widx[b];
        int ci = cidx[b];
        const float4* wp = (const float4*)(node_emb + (size_t)wi * D + quarter * 32);
        const float4* cp = (const float4*)(node_emb + (size_t)ci * D + quarter * 32);
        float2* dst = (float2*)sPW;    // pair index = d*BM + col
        int col = r ^ (quarter << 3);  // swizzle: (d>>5)==quarter in this range
        #pragma unroll
        for (int j = 0; j < 8; j++) {
            float4 a  = wp[j];
            float4 bb = cp[j];
            int dbase = quarter * 32 + j * 4;
            dst[(dbase + 0) * BM + col] = make_float2(a.x * bb.x, a.x);
            dst[(dbase + 1) * BM + col] = make_float2(a.y * bb.y, a.y);
            dst[(dbase + 2) * BM + col] = make_float2(a.z * bb.z, a.z);
            dst[(dbase + 3) * BM + col] = make_float2(a.w * bb.w, a.w);
        }
    }
    __syncthreads();

    // ---------------- Phase 2: dual GEMM via packed f32x2 ----------------
    // thread tile: 4 batch rows x 4 k columns. Per thread-d: 1 LDG.128 (W) +
    // 2 LDS.128 (four row-pairs, 32B contiguous & aligned; row swizzled by d).
    const int tx = tid & 15;       // k-group
    const int ty = tid >> 4;       // b-group
    const int kb = tx * 4;
    const int bb = ty * 4;

    unsigned long long acc[4][4];
    #pragma unroll
    for (int i = 0; i < 4; i++)
        #pragma unroll
        for (int j = 0; j < 4; j++) acc[i][j] = 0ull;

    #pragma unroll
    for (int dc = 0; dc < 4; dc++) {
        const int xb = bb ^ (dc << 3);     // swizzled row base for this d-chunk
        #pragma unroll 4
        for (int dd = 0; dd < 32; dd++) {
            const int d = dc * 32 + dd;
            const float4 wv = __ldg((const float4*)(g_WT + (size_t)d * K + kb));
            unsigned long long w0 = dup2(wv.x);
            unsigned long long w1 = dup2(wv.y);
            unsigned long long w2 = dup2(wv.z);
            unsigned long long w3 = dup2(wv.w);
            const ulonglong2* pw2 =
                (const ulonglong2*)(sPW + (size_t)(d * BM + xb) * 2);
            ulonglong2 A01 = pw2[0];
            ulonglong2 A23 = pw2[1];
            acc[0][0] = fma2(A01.x, w0, acc[0][0]);
            acc[0][1] = fma2(A01.x, w1, acc[0][1]);
            acc[0][2] = fma2(A01.x, w2, acc[0][2]);
            acc[0][3] = fma2(A01.x, w3, acc[0][3]);
            acc[1][0] = fma2(A01.y, w0, acc[1][0]);
            acc[1][1] = fma2(A01.y, w1, acc[1][1]);
            acc[1][2] = fma2(A01.y, w2, acc[1][2]);
            acc[1][3] = fma2(A01.y, w3, acc[1][3]);
            acc[2][0] = fma2(A23.x, w0, acc[2][0]);
            acc[2][1] = fma2(A23.x, w1, acc[2][1]);
            acc[2][2] = fma2(A23.x, w2, acc[2][2]);
            acc[2][3] = fma2(A23.x, w3, acc[2][3]);
            acc[3][0] = fma2(A23.y, w0, acc[3][0]);
            acc[3][1] = fma2(A23.y, w1, acc[3][1]);
            acc[3][2] = fma2(A23.y, w2, acc[3][2]);
            acc[3][3] = fma2(A23.y, w3, acc[3][3]);
        }
    }
    __syncthreads();   // all phase-2 reads of sPW done before overlay

    // NOTE: the swizzle maps rows within each d-chunk; accumulators correspond
    // to the UN-swizzled rows bb..bb+3 XOR'd per chunk — but since we XOR the
    // READ base identically to the WRITE base, thread (ty,tx) accumulates rows
    // (bb ^ x) with the data of rows (bb ^ x): i.e., acc[i] holds logits for
    // batch row (bb ^ x) + i... which varies per chunk! To keep correctness,
    // the XOR must be applied consistently: data for row R at d is stored at
    // col R ^ x(d); reading col (bb ^ x(d)) + i yields row ((bb ^ x(d)) + i) ^ x(d).
    // Because bb is a multiple of 4 and x is a multiple of 8, (bb^x)+i = (bb+i)^x,
    // and ((bb+i)^x)^x = bb+i. So acc[i] is exactly row bb+i for every chunk. ✓

    // ---------------- Phase 3: dump q / prior logits (padded, vectorized) -----
    float* sQ = smem;                     // [BM][QS] = 17408B
    float* sP = smem + BM * QS;           // [BM][QS]
    #pragma unroll
    for (int i = 0; i < 4; i++) {
        float2 t0 = unpk(acc[i][0]);
        float2 t1 = unpk(acc[i][1]);
        float2 t2 = unpk(acc[i][2]);
        float2 t3 = unpk(acc[i][3]);
        *(float4*)&sQ[(bb + i) * QS + kb] = make_float4(t0.x, t1.x, t2.x, t3.x);
        *(float4*)&sP[(bb + i) * QS + kb] = make_float4(t0.y, t1.y, t2.y, t3.y);
    }
    __syncthreads();

    // ---------------- Phase 4+5: per-warp rows (no cross-warp sync) -----------
    float lacc = 0.0f;
    for (int j = 0; j < 8; j++) {
        int r = warp * 8 + j;
        int b = b0 + r;
        if (b >= Btot) break;

        // ---- issue all independent loads first (latency overlap) ----
        int ci = cidx[b];
        int n0 = negidx[(size_t)b * NNEG + 0];
        int n1 = negidx[(size_t)b * NNEG + 1];
        int n2 = negidx[(size_t)b * NNEG + 2];
        int n3 = negidx[(size_t)b * NNEG + 3];
        int n4 = negidx[(size_t)b * NNEG + 4];
        float4 cv = *(const float4*)(ctx_emb + (size_t)ci * D + (lane << 2));
        float4 v0 = *(const float4*)(ctx_emb + (size_t)n0 * D + (lane << 2));
        float4 v1 = *(const float4*)(ctx_emb + (size_t)n1 * D + (lane << 2));
        float4 v2 = *(const float4*)(ctx_emb + (size_t)n2 * D + (lane << 2));
        float4 v3 = *(const float4*)(ctx_emb + (size_t)n3 * D + (lane << 2));
        float4 v4 = *(const float4*)(ctx_emb + (size_t)n4 * D + (lane << 2));
        float g1 = __ldcs(gumbel + (size_t)b * K + lane);
        float g2 = __ldcs(gumbel + (size_t)b * K + 32 + lane);
        float q1 = sQ[r * QS + lane];
        float q2 = sQ[r * QS + 32 + lane];
        float p1 = sP[r * QS + lane];
        float p2 = sP[r * QS + 32 + lane];

        // ---- argmax(q + gumbel) first, so the W[k*] gather flies early ----
        float av = q1 + g1;
        int   ai = lane;
        {
            float a2v = q2 + g2;
            if (a2v > av) { av = a2v; ai = lane + 32; }
        }
        float    mv  = wmax(av);
        unsigned msk = __ballot_sync(FULLMASK, av == mv);
        int      kst = __shfl_sync(FULLMASK, ai, __ffs(msk) - 1);
        float4 wv = *(const float4*)(Wg + (size_t)kst * D + (lane << 2));

        // ---- softmax(q) ----
        float mq  = wmax(fmaxf(q1, q2));
        float e1  = __expf(q1 - mq);
        float e2  = __expf(q2 - mq);
        float inv = __fdividef(1.0f, wsum(e1 + e2));
        __stcs(outq + (size_t)b * K + lane,      e1 * inv);
        __stcs(outq + (size_t)b * K + 32 + lane, e2 * inv);

        // ---- softmax(prior) ----
        float mp = wmax(fmaxf(p1, p2));
        float f1 = __expf(p1 - mp);
        float f2 = __expf(p2 - mp);
        float ip = __fdividef(1.0f, wsum(f1 + f2));
        __stcs(outp + (size_t)b * K + lane,      f1 * ip);
        __stcs(outp + (size_t)b * K + 32 + lane, f2 * ip);

        // ---- loss dots with W[k*] ----
        float s0 = dot4(wv, cv);
        float s1 = dot4(wv, v0);
        float s2 = dot4(wv, v1);
        float s3 = dot4(wv, v2);
        float s4 = dot4(wv, v3);
        float s5 = dot4(wv, v4);
        s0 = wsum(s0); s1 = wsum(s1); s2 = wsum(s2);
        s3 = wsum(s3); s4 = wsum(s4); s5 = wsum(s5);

        float term = log_sigmoid(s0);
        float nsum = log_sigmoid(-s1) + log_sigmoid(-s2) + log_sigmoid(-s3)
                   + log_sigmoid(-s4) + log_sigmoid(-s5);
        term = fmaf(nsum, 1.0f / (float)NNEG, term);
        if (lane == 0) lacc += term;
    }

    // ---------------- Block partial + last-block deterministic reduce ---------
    if (lane == 0) sred[warp] = lacc;
    __syncthreads();
    if (tid == 0) {
        float s = 0.0f;
        #pragma unroll
        for (int i = 0; i < 8; i++) s += sred[i];
        g_partials[blockIdx.x] = s;
        __threadfence();
        unsigned t = atomicAdd(&g_counter, 1u);
        s_last = (t == gridDim.x - 1) ? 1 : 0;
    }
    __syncthreads();

    if (s_last) {
        float s = 0.0f;
        for (int i = tid; i < (int)gridDim.x; i += NTHREADS)
            s += __ldcg(&g_partials[i]);
        smem[tid] = s;
        __syncthreads();
        #pragma unroll
        for (int o = NTHREADS / 2; o > 0; o >>= 1) {
            if (tid < o) smem[tid] += smem[tid + o];
            __syncthreads();
        }
        if (tid == 0) {
            out0[0] = -smem[0] * invB;
            g_counter = 0;   // reset for next (graph-replayed) launch
        }
    }
}

// =============================================================================
extern "C" void kernel_launch(void* const* d_in, const int* in_sizes, int n_in,
                              void* d_out, int out_size)
{
    const int*   w        = (const int*)  d_in[0];
    const int*   c        = (const int*)  d_in[1];
    const int*   neg      = (const int*)  d_in[2];
    // d_in[3] = temp (==1): only rescales the argmax input -> provably irrelevant
    const float* gumbel   = (const float*)d_in[4];
    const float* node_emb = (const float*)d_in[5];
    const float* ctx_emb  = (const float*)d_in[6];
    const float* Wg       = (const float*)d_in[7];

    const int B = in_sizes[0];

    float* out       = (float*)d_out;
    float* out_q     = out + 1;
    float* out_prior = out + 1 + (size_t)B * K;

    int nb = (B + BM - 1) / BM;     // 2048 for B=131072
    if (nb > MAXBLOCKS) nb = MAXBLOCKS;

    cudaFuncSetAttribute(gcn_gumbel_mega,
                         cudaFuncAttributeMaxDynamicSharedMemorySize, SMEM_BYTES);

    gcn_wt_setup<<<(K * D / 4 + 255) / 256, 256>>>(Wg);
    gcn_gumbel_mega<<<nb, NTHREADS, SMEM_BYTES>>>(
        w, c, neg, gumbel, node_emb, ctx_emb, Wg,
        out, out_q, out_prior, B, 1.0f / (float)B);
}